// round 1
// baseline (speedup 1.0000x reference)
#include <cuda_runtime.h>

// GraphAttentionLayer: out = softmax(leaky_relu(Wh @ Wh^T)) @ Wh, Wh = h @ W
// N=8192, IN_F=256, OUT_F=128. Flash-attention formulation, fp32.

#define N_NODES 8192
#define DIN 256
#define D 128           // head dim = OUT_F
#define BM 64           // query rows per CTA
#define BN 64           // key rows per tile
#define NEG_SLOPE 0.2f

// Scratch for Wh (device global: no allocations allowed)
__device__ __align__(16) float g_Wh[N_NODES * D];

// ---------------------------------------------------------------------------
// Kernel 1: Wh = h @ W   (8192x256 @ 256x128), fp32
// 128 threads per block, 8 rows per block. W column read coalesced per thread.
// ---------------------------------------------------------------------------
__global__ __launch_bounds__(128) void wh_kernel(const float* __restrict__ h,
                                                 const float* __restrict__ W) {
    __shared__ float hs[8][DIN];
    const int r0 = blockIdx.x * 8;
    const int tid = threadIdx.x;  // 0..127 (= output column)

    for (int i = tid; i < 8 * DIN; i += 128)
        hs[i >> 8][i & 255] = h[r0 * DIN + i];
    __syncthreads();

    float acc[8];
#pragma unroll
    for (int r = 0; r < 8; r++) acc[r] = 0.f;

    for (int k = 0; k < DIN; k++) {
        float w = W[k * D + tid];
#pragma unroll
        for (int r = 0; r < 8; r++) acc[r] = fmaf(hs[r][k], w, acc[r]);
    }
#pragma unroll
    for (int r = 0; r < 8; r++) g_Wh[(r0 + r) * D + tid] = acc[r];
}

// ---------------------------------------------------------------------------
// Kernel 2: flash attention over Wh with leaky_relu on scores.
// 256 threads (16x16 grid of threads), BM=64 query rows per CTA.
// SMEM: Qt[k][r] (transposed), Kt[k][c] (transposed), Vn[j][k] (natural),
//       St[c][r] (transposed P). ~121 KB dynamic, 1 CTA/SM.
// Row stats (m, l) are replicated in registers across each 16-lane half-warp
// that owns those 4 rows: no shared-memory softmax state at all.
// ---------------------------------------------------------------------------
__global__ __launch_bounds__(256, 1) void attn_kernel(const float* __restrict__ Wh,
                                                      float* __restrict__ out) {
    extern __shared__ float sm[];
    float* Qt = sm;                       // [128][BM+4]
    float* Kt = Qt + D * (BM + 4);        // [128][BN+4]
    float* Vn = Kt + D * (BN + 4);        // [BN][D+4]
    float* St = Vn + BN * (D + 4);        // [BN][BM+4]  (P transposed)

    const int tid = threadIdx.x;
    const int tx = tid & 15;              // 0..15 -> key cols (QK) / out cols (PV)
    const int ty = tid >> 4;              // 0..15 -> query rows (4 per thread)
    const int q0 = blockIdx.x * BM;

    // ---- Load Q tile transposed (once) ----
#pragma unroll
    for (int it = 0; it < 8; it++) {
        int i4 = tid + it * 256;          // 0..2047 float4 slots
        int r = i4 >> 5;                  // 0..63
        int k4 = (i4 & 31) << 2;          // 0,4,..124
        float4 v = *(const float4*)&Wh[(q0 + r) * D + k4];
        Qt[(k4 + 0) * (BM + 4) + r] = v.x;
        Qt[(k4 + 1) * (BM + 4) + r] = v.y;
        Qt[(k4 + 2) * (BM + 4) + r] = v.z;
        Qt[(k4 + 3) * (BM + 4) + r] = v.w;
    }

    // ---- Accumulators & running softmax stats (register-resident) ----
    float O[4][8];
#pragma unroll
    for (int i = 0; i < 4; i++)
#pragma unroll
        for (int w = 0; w < 8; w++) O[i][w] = 0.f;
    float m_run[4], l_run[4];
#pragma unroll
    for (int i = 0; i < 4; i++) { m_run[i] = -1e30f; l_run[i] = 0.f; }

    for (int kt = 0; kt < N_NODES / BN; kt++) {
        __syncthreads();  // Qt ready (1st iter) / prev PV reads done

        // ---- Load K tile transposed + V tile natural ----
        const float* Kg = Wh + (size_t)kt * BN * D;
#pragma unroll
        for (int it = 0; it < 8; it++) {
            int i4 = tid + it * 256;
            int r = i4 >> 5;
            int k4 = (i4 & 31) << 2;
            float4 v = *(const float4*)&Kg[r * D + k4];
            Kt[(k4 + 0) * (BN + 4) + r] = v.x;
            Kt[(k4 + 1) * (BN + 4) + r] = v.y;
            Kt[(k4 + 2) * (BN + 4) + r] = v.z;
            Kt[(k4 + 3) * (BN + 4) + r] = v.w;
            *(float4*)&Vn[r * (D + 4) + k4] = v;
        }
        __syncthreads();

        // ---- S = Q @ K^T (4x4 per thread) ----
        float s[4][4];
#pragma unroll
        for (int i = 0; i < 4; i++)
#pragma unroll
            for (int j = 0; j < 4; j++) s[i][j] = 0.f;

        for (int k = 0; k < D; k++) {
            float4 a = *(float4*)&Qt[k * (BM + 4) + ty * 4];
            float4 b = *(float4*)&Kt[k * (BN + 4) + tx * 4];
            float af[4] = {a.x, a.y, a.z, a.w};
            float bf[4] = {b.x, b.y, b.z, b.w};
#pragma unroll
            for (int i = 0; i < 4; i++)
#pragma unroll
                for (int j = 0; j < 4; j++)
                    s[i][j] = fmaf(af[i], bf[j], s[i][j]);
        }

        // ---- leaky_relu ----
#pragma unroll
        for (int i = 0; i < 4; i++)
#pragma unroll
            for (int j = 0; j < 4; j++)
                s[i][j] = s[i][j] > 0.f ? s[i][j] : NEG_SLOPE * s[i][j];

        // ---- Online softmax: row max + exp + row sum, per half-warp ----
        float alpha[4], p[4][4];
#pragma unroll
        for (int i = 0; i < 4; i++) {
            float v = fmaxf(fmaxf(s[i][0], s[i][1]), fmaxf(s[i][2], s[i][3]));
#pragma unroll
            for (int off = 8; off; off >>= 1)
                v = fmaxf(v, __shfl_xor_sync(0xffffffffu, v, off));
            float mn = fmaxf(m_run[i], v);
            alpha[i] = __expf(m_run[i] - mn);
            m_run[i] = mn;
            float ps = 0.f;
#pragma unroll
            for (int j = 0; j < 4; j++) {
                p[i][j] = __expf(s[i][j] - mn);
                ps += p[i][j];
            }
#pragma unroll
            for (int off = 8; off; off >>= 1)
                ps += __shfl_xor_sync(0xffffffffu, ps, off);
            l_run[i] = l_run[i] * alpha[i] + ps;
        }

        // ---- Write P transposed to SMEM ----
#pragma unroll
        for (int j = 0; j < 4; j++) {
            float4 pv = make_float4(p[0][j], p[1][j], p[2][j], p[3][j]);
            *(float4*)&St[(tx * 4 + j) * (BM + 4) + ty * 4] = pv;
        }

        // ---- Rescale O ----
#pragma unroll
        for (int i = 0; i < 4; i++)
#pragma unroll
            for (int w = 0; w < 8; w++) O[i][w] *= alpha[i];

        __syncthreads();  // St complete

        // ---- O += P @ V (4 rows x 8 cols per thread) ----
#pragma unroll 4
        for (int j = 0; j < BN; j++) {
            float4 pj = *(float4*)&St[j * (BM + 4) + ty * 4];
            float4 v0 = *(float4*)&Vn[j * (D + 4) + tx * 8];
            float4 v1 = *(float4*)&Vn[j * (D + 4) + tx * 8 + 4];
            float pf[4] = {pj.x, pj.y, pj.z, pj.w};
            float vf[8] = {v0.x, v0.y, v0.z, v0.w, v1.x, v1.y, v1.z, v1.w};
#pragma unroll
            for (int i = 0; i < 4; i++)
#pragma unroll
                for (int w = 0; w < 8; w++)
                    O[i][w] = fmaf(pf[i], vf[w], O[i][w]);
        }
    }

    // ---- Epilogue: normalize and store ----
#pragma unroll
    for (int i = 0; i < 4; i++) {
        float inv = 1.f / l_run[i];
        int r = q0 + ty * 4 + i;
        float4 o0 = make_float4(O[i][0] * inv, O[i][1] * inv, O[i][2] * inv, O[i][3] * inv);
        float4 o1 = make_float4(O[i][4] * inv, O[i][5] * inv, O[i][6] * inv, O[i][7] * inv);
        *(float4*)&out[r * D + tx * 8] = o0;
        *(float4*)&out[r * D + tx * 8 + 4] = o1;
    }
}

// ---------------------------------------------------------------------------
extern "C" void kernel_launch(void* const* d_in, const int* in_sizes, int n_in,
                              void* d_out, int out_size) {
    const float* h = (const float*)d_in[0];
    // d_in[1] = adj (unused by the math; never read)
    const float* W = (const float*)d_in[2];
    float* out = (float*)d_out;

    // Dynamic SMEM for attn_kernel:
    // Qt 128*68 + Kt 128*68 + Vn 64*132 + St 64*68 floats = 30208 floats
    const int smem_bytes = (D * (BM + 4) + D * (BN + 4) + BN * (D + 4) + BN * (BM + 4)) * 4;
    cudaFuncSetAttribute(attn_kernel, cudaFuncAttributeMaxDynamicSharedMemorySize, smem_bytes);

    float* Wh_ptr;
    cudaGetSymbolAddress((void**)&Wh_ptr, g_Wh);

    wh_kernel<<<N_NODES / 8, 128>>>(h, W);
    attn_kernel<<<N_NODES / BM, 256, smem_bytes>>>(Wh_ptr, out);
}

// round 6
// speedup vs baseline: 4.0721x; 4.0721x over previous
#include <cuda_runtime.h>
#include <cuda_bf16.h>
#include <cstdint>

// GraphAttentionLayer: out = softmax(leaky_relu(Wh @ Wh^T)) @ Wh, Wh = h @ W
// N=8192, DIN=256, D=128. Flash attention on warp-level bf16 HMMA
// (mma.sync.m16n8k16 — arch-portable PTX; tcgen05 is unavailable because the
// harness emits family-generic compute_103 PTX). fp32 softmax, V split into
// bf16 hi+lo so PV keeps ~fp32 precision. Split-K=2 over keys + combine.

#define NN 8192
#define DIN 256
#define D 128
#define BM 128          // query rows per CTA (16 per warp, 8 warps)
#define BN 64           // key rows per tile
#define SPLIT 2
#define KT_PER (NN / BN / SPLIT)   // 64 key tiles per CTA
#define NEG_SLOPE 0.2f

// ---------------- device scratch (no allocations allowed) ----------------
__device__ __align__(16) float          g_Wh[NN * D];       // fp32 Wh
__device__ __align__(16) __nv_bfloat16  g_Kbf[NN * D];      // bf16 Wh (Q and K)
__device__ __align__(16) __nv_bfloat16  g_VhiT[D * NN];     // V^T hi (dim-major)
__device__ __align__(16) __nv_bfloat16  g_VloT[D * NN];     // V^T lo
__device__ __align__(16) float          g_Opart[SPLIT * NN * D];
__device__ float g_m[SPLIT * NN];
__device__ float g_l[SPLIT * NN];

// ---------------- warp-MMA helpers (portable PTX, sm_80+) ----------------
__device__ __forceinline__ uint32_t smem_u32(const void* p) {
    uint32_t a;
    asm("{ .reg .u64 t; cvta.to.shared.u64 t, %1; cvt.u32.u64 %0, t; }" : "=r"(a) : "l"(p));
    return a;
}
__device__ __forceinline__ void ldsm4(uint32_t r[4], uint32_t addr) {
    asm volatile("ldmatrix.sync.aligned.m8n8.x4.shared.b16 {%0,%1,%2,%3}, [%4];"
                 : "=r"(r[0]), "=r"(r[1]), "=r"(r[2]), "=r"(r[3]) : "r"(addr));
}
__device__ __forceinline__ void mma16816(float d[4], const uint32_t a[4],
                                         uint32_t b0, uint32_t b1) {
    asm volatile("mma.sync.aligned.m16n8k16.row.col.f32.bf16.bf16.f32 "
                 "{%0,%1,%2,%3}, {%4,%5,%6,%7}, {%8,%9}, {%0,%1,%2,%3};"
                 : "+f"(d[0]), "+f"(d[1]), "+f"(d[2]), "+f"(d[3])
                 : "r"(a[0]), "r"(a[1]), "r"(a[2]), "r"(a[3]), "r"(b0), "r"(b1));
}
__device__ __forceinline__ uint32_t pack_bf16x2(float lo, float hi) {
    uint32_t r;
    asm("cvt.rn.bf16x2.f32 %0, %1, %2;" : "=r"(r) : "f"(hi), "f"(lo));
    return r;
}

// SMEM byte offsets (dynamic, 81920 B total)
#define SM_Q  0          // 128 rows x 16 chunks(16B)  = 32 KB  (bf16, row-major, swizzled)
#define SM_K  32768      //  64 rows x 16 chunks       = 16 KB
#define SM_VH 49152      // 128 rows(d) x 8 chunks     = 16 KB  (V^T hi)
#define SM_VL 65536      // 128 rows(d) x 8 chunks     = 16 KB  (V^T lo)
#define SM_TOTAL 81920

// ---------------------------------------------------------------------------
// Kernel 1: Wh = h @ W (fp32), also emits bf16 copy for Q/K
// ---------------------------------------------------------------------------
__global__ __launch_bounds__(128) void wh_kernel(const float* __restrict__ h,
                                                 const float* __restrict__ W) {
    __shared__ float hs[8][DIN];
    const int r0 = blockIdx.x * 8;
    const int tid = threadIdx.x;
    for (int i = tid; i < 8 * DIN; i += 128) hs[i >> 8][i & 255] = h[r0 * DIN + i];
    __syncthreads();
    float acc[8];
#pragma unroll
    for (int r = 0; r < 8; r++) acc[r] = 0.f;
    for (int k = 0; k < DIN; k++) {
        float w = W[k * D + tid];
#pragma unroll
        for (int r = 0; r < 8; r++) acc[r] = fmaf(hs[r][k], w, acc[r]);
    }
#pragma unroll
    for (int r = 0; r < 8; r++) {
        g_Wh[(r0 + r) * D + tid] = acc[r];
        g_Kbf[(r0 + r) * D + tid] = __float2bfloat16(acc[r]);
    }
}

// ---------------------------------------------------------------------------
// Kernel 2: transpose Wh -> VhiT/VloT (bf16 hi/lo split, dim-major)
// ---------------------------------------------------------------------------
__global__ __launch_bounds__(256) void conv_kernel() {
    __shared__ float ts[32][33];
    const int n0 = blockIdx.x * 32, d0 = blockIdx.y * 32;
    const int tx = threadIdx.x, ty = threadIdx.y;   // 32 x 8
    for (int r = ty; r < 32; r += 8) ts[r][tx] = g_Wh[(n0 + r) * D + d0 + tx];
    __syncthreads();
    for (int dd = ty; dd < 32; dd += 8) {
        float v = ts[tx][dd];
        __nv_bfloat16 hi = __float2bfloat16(v);
        __nv_bfloat16 lo = __float2bfloat16(v - __bfloat162float(hi));
        g_VhiT[(size_t)(d0 + dd) * NN + n0 + tx] = hi;
        g_VloT[(size_t)(d0 + dd) * NN + n0 + tx] = lo;
    }
}

// ---------------------------------------------------------------------------
// Kernel 3: flash attention, warp HMMA. grid (64, SPLIT), 256 threads.
// Warp w owns query rows q0+16w..q0+16w+15.
// Fragment layouts (mma.m16n8k16): per thread,
//   A: a0=(r,k2) a1=(r+8,k2) a2=(r,k2+8) a3=(r+8,k2+8), r=lane>>2, k2=2*(lane&3)
//   B: b0=(k2,n) b1=(k2+8,n), n=lane>>2
//   C: c0,c1=(r, 2n..+1)  c2,c3=(r+8, 2n..+1)
// ---------------------------------------------------------------------------
__global__ __launch_bounds__(256, 1) void attn_kernel() {
    extern __shared__ char smem[];
    const uint32_t sbase = smem_u32(smem);
    const int tid = threadIdx.x;
    const int wid = tid >> 5;
    const int lane = tid & 31;
    const int q0 = blockIdx.x * BM;
    const int split = blockIdx.y;

    // ---- load Q tile into smem (swizzled) ----
    for (int i = tid; i < 2048; i += 256) {           // 128 rows x 16 chunks
        int row = i >> 4, ch = i & 15;
        const uint4 v = *(const uint4*)(g_Kbf + (size_t)(q0 + row) * D + ch * 8);
        *(uint4*)(smem + SM_Q + row * 256 + ((ch ^ (row & 7)) << 4)) = v;
    }
    __syncthreads();

    // ---- Q fragments into registers (held for whole kernel) ----
    uint32_t qf[8][4];
    {
        // A ldmatrix addressing: lane l -> row = m0 + (l & 15), chunk = 2k + (l >> 4)
        int arow = 16 * wid + (lane & 15);
        int achb = lane >> 4;
#pragma unroll
        for (int k = 0; k < 8; k++) {
            int ch = 2 * k + achb;
            uint32_t addr = sbase + SM_Q + arow * 256 + ((ch ^ (arow & 7)) << 4);
            ldsm4(qf[k], addr);
        }
    }

    // B-fragment ldmatrix lane addressing:
    // lane l -> row = n0 + ((l>>4)<<3) + (l&7), chunk = 2k + ((l>>3)&1)
    const int brow_off = ((lane >> 4) << 3) + (lane & 7);
    const int bch_off = (lane >> 3) & 1;

    float o[16][4];
#pragma unroll
    for (int n = 0; n < 16; n++)
#pragma unroll
        for (int j = 0; j < 4; j++) o[n][j] = 0.f;
    float m0r = -1e30f, m1r = -1e30f, l0r = 0.f, l1r = 0.f;

    for (int kt = 0; kt < KT_PER; kt++) {
        __syncthreads();   // previous tile's smem fully consumed

        // ---- load K, VhiT, VloT tiles (swizzled) ----
        const int key0 = split * (NN / SPLIT) + kt * BN;
        for (int i = tid; i < 1024; i += 256) {       // K: 64 rows x 16 chunks
            int row = i >> 4, ch = i & 15;
            const uint4 v = *(const uint4*)(g_Kbf + (size_t)(key0 + row) * D + ch * 8);
            *(uint4*)(smem + SM_K + row * 256 + ((ch ^ (row & 7)) << 4)) = v;
        }
        for (int i = tid; i < 1024; i += 256) {       // VhiT: 128 rows x 8 chunks
            int row = i >> 3, ch = i & 7;
            const uint4 v = *(const uint4*)(g_VhiT + (size_t)row * NN + key0 + ch * 8);
            *(uint4*)(smem + SM_VH + row * 128 + ((ch ^ (row & 7)) << 4)) = v;
        }
        for (int i = tid; i < 1024; i += 256) {       // VloT
            int row = i >> 3, ch = i & 7;
            const uint4 v = *(const uint4*)(g_VloT + (size_t)row * NN + key0 + ch * 8);
            *(uint4*)(smem + SM_VL + row * 128 + ((ch ^ (row & 7)) << 4)) = v;
        }
        __syncthreads();

        // ---- S = Q @ K^T : 8 ntiles (n8) x 8 ktiles (k16) ----
        float s[8][4];
#pragma unroll
        for (int n = 0; n < 8; n++)
#pragma unroll
            for (int j = 0; j < 4; j++) s[n][j] = 0.f;
#pragma unroll
        for (int np = 0; np < 4; np++) {              // pair of n8 tiles
            int brow = 16 * np + brow_off;
            uint32_t rbase = sbase + SM_K + brow * 256;
            int bsw = brow & 7;
#pragma unroll
            for (int k = 0; k < 8; k++) {
                int ch = 2 * k + bch_off;
                uint32_t b[4];
                ldsm4(b, rbase + ((ch ^ bsw) << 4));
                mma16816(s[2 * np], qf[k], b[0], b[1]);
                mma16816(s[2 * np + 1], qf[k], b[2], b[3]);
            }
        }

        // ---- leaky_relu + online softmax (rows r=lane>>2 and r+8) ----
#pragma unroll
        for (int n = 0; n < 8; n++)
#pragma unroll
            for (int j = 0; j < 4; j++)
                s[n][j] = fmaxf(s[n][j], NEG_SLOPE * s[n][j]);

        float mx0 = -1e30f, mx1 = -1e30f;
#pragma unroll
        for (int n = 0; n < 8; n++) {
            mx0 = fmaxf(mx0, fmaxf(s[n][0], s[n][1]));
            mx1 = fmaxf(mx1, fmaxf(s[n][2], s[n][3]));
        }
        mx0 = fmaxf(mx0, __shfl_xor_sync(0xffffffffu, mx0, 1));
        mx0 = fmaxf(mx0, __shfl_xor_sync(0xffffffffu, mx0, 2));
        mx1 = fmaxf(mx1, __shfl_xor_sync(0xffffffffu, mx1, 1));
        mx1 = fmaxf(mx1, __shfl_xor_sync(0xffffffffu, mx1, 2));

        float mn0 = fmaxf(m0r, mx0), mn1 = fmaxf(m1r, mx1);
        float a0 = __expf(m0r - mn0), a1 = __expf(m1r - mn1);
        m0r = mn0; m1r = mn1;

        // lazy rescale of O (running max rarely grows for peaked softmax)
        if (kt > 0) {
            unsigned need = __ballot_sync(0xffffffffu, (a0 != 1.f) || (a1 != 1.f));
            if (need) {
#pragma unroll
                for (int n = 0; n < 16; n++) {
                    o[n][0] *= a0; o[n][1] *= a0;
                    o[n][2] *= a1; o[n][3] *= a1;
                }
            }
        }

        float ps0 = 0.f, ps1 = 0.f;
#pragma unroll
        for (int n = 0; n < 8; n++) {
            s[n][0] = __expf(s[n][0] - mn0);
            s[n][1] = __expf(s[n][1] - mn0);
            s[n][2] = __expf(s[n][2] - mn1);
            s[n][3] = __expf(s[n][3] - mn1);
            ps0 += s[n][0] + s[n][1];
            ps1 += s[n][2] + s[n][3];
        }
        ps0 += __shfl_xor_sync(0xffffffffu, ps0, 1);
        ps0 += __shfl_xor_sync(0xffffffffu, ps0, 2);
        ps1 += __shfl_xor_sync(0xffffffffu, ps1, 1);
        ps1 += __shfl_xor_sync(0xffffffffu, ps1, 2);
        l0r = l0r * a0 + ps0;
        l1r = l1r * a1 + ps1;

        // ---- P fragments: S accum frag -> A operand frag (bf16) ----
        uint32_t pA[4][4];    // 4 k16-tiles over seq(=BN), A layout
#pragma unroll
        for (int j = 0; j < 4; j++) {
            pA[j][0] = pack_bf16x2(s[2 * j][0], s[2 * j][1]);
            pA[j][1] = pack_bf16x2(s[2 * j][2], s[2 * j][3]);
            pA[j][2] = pack_bf16x2(s[2 * j + 1][0], s[2 * j + 1][1]);
            pA[j][3] = pack_bf16x2(s[2 * j + 1][2], s[2 * j + 1][3]);
        }

        // ---- O += P @ Vhi^T, P @ Vlo^T : 8 npairs (d) x 4 ktiles (seq) ----
#pragma unroll
        for (int np = 0; np < 8; np++) {
            int brow = 16 * np + brow_off;
            int bsw = brow & 7;
            uint32_t rh = sbase + SM_VH + brow * 128;
            uint32_t rl = sbase + SM_VL + brow * 128;
#pragma unroll
            for (int j = 0; j < 4; j++) {
                int ch = 2 * j + bch_off;
                uint32_t sw = (uint32_t)((ch ^ bsw) << 4);
                uint32_t b[4];
                ldsm4(b, rh + sw);
                mma16816(o[2 * np], pA[j], b[0], b[1]);
                mma16816(o[2 * np + 1], pA[j], b[2], b[3]);
                ldsm4(b, rl + sw);
                mma16816(o[2 * np], pA[j], b[0], b[1]);
                mma16816(o[2 * np + 1], pA[j], b[2], b[3]);
            }
        }
    }

    // ---- epilogue: dump unnormalized O + (m, l) partials ----
    const int r0 = q0 + 16 * wid + (lane >> 2);
    const int cb = 2 * (lane & 3);
    float* ob = &g_Opart[((size_t)split * NN + r0) * D];
#pragma unroll
    for (int n = 0; n < 16; n++) {
        *(float2*)&ob[8 * n + cb] = make_float2(o[n][0], o[n][1]);
        *(float2*)&ob[8 * D + 8 * n + cb] = make_float2(o[n][2], o[n][3]);  // row r0+8
    }
    if ((lane & 3) == 0) {
        g_m[split * NN + r0] = m0r;
        g_l[split * NN + r0] = l0r;
        g_m[split * NN + r0 + 8] = m1r;
        g_l[split * NN + r0 + 8] = l1r;
    }
}

// ---------------------------------------------------------------------------
// Kernel 4: combine the SPLIT partials
// ---------------------------------------------------------------------------
__global__ __launch_bounds__(128) void combine_kernel(float* __restrict__ out) {
    const int r = blockIdx.x, c = threadIdx.x;
    float m0 = g_m[r], m1 = g_m[NN + r];
    float m = fmaxf(m0, m1);
    float w0 = __expf(m0 - m), w1 = __expf(m1 - m);
    float l = g_l[r] * w0 + g_l[NN + r] * w1;
    float o = g_Opart[(size_t)r * D + c] * w0 + g_Opart[(size_t)(NN + r) * D + c] * w1;
    out[(size_t)r * D + c] = o / l;
}

// ---------------------------------------------------------------------------
extern "C" void kernel_launch(void* const* d_in, const int* in_sizes, int n_in,
                              void* d_out, int out_size) {
    const float* h = (const float*)d_in[0];
    // d_in[1] = adj: unused by the math, never touched
    const float* W = (const float*)d_in[2];
    float* out = (float*)d_out;

    cudaFuncSetAttribute(attn_kernel, cudaFuncAttributeMaxDynamicSharedMemorySize, SM_TOTAL);

    wh_kernel<<<NN / 8, 128>>>(h, W);
    conv_kernel<<<dim3(NN / 32, D / 32), dim3(32, 8)>>>();
    attn_kernel<<<dim3(NN / BM, SPLIT), 256, SM_TOTAL>>>();
    combine_kernel<<<NN, 128>>>(out);
}

// round 8
// speedup vs baseline: 7.8269x; 1.9221x over previous
#include <cuda_runtime.h>
#include <cuda_bf16.h>
#include <cstdint>

// GraphAttentionLayer: out = softmax(leaky_relu(Wh @ Wh^T)) @ Wh, Wh = h @ W
// N=8192, DIN=256, D=128. Flash attention on warp-level bf16 HMMA with
// cp.async double-buffered K/V tiles. fp32 softmax, V split into bf16 hi+lo
// so PV keeps ~fp32 precision. Split-K=2 over keys + combine.

#define NN 8192
#define DIN 256
#define D 128
#define BM 128          // query rows per CTA (16 per warp, 8 warps)
#define BN 64           // key rows per tile
#define SPLIT 2
#define KT_PER (NN / BN / SPLIT)   // 64 key tiles per CTA
#define NEG_SLOPE 0.2f

// ---------------- device scratch (no allocations allowed) ----------------
__device__ __align__(16) float          g_Wh[NN * D];       // fp32 Wh
__device__ __align__(16) __nv_bfloat16  g_Kbf[NN * D];      // bf16 Wh (Q and K)
__device__ __align__(16) __nv_bfloat16  g_VhiT[D * NN];     // V^T hi (dim-major)
__device__ __align__(16) __nv_bfloat16  g_VloT[D * NN];     // V^T lo
__device__ __align__(16) float          g_Opart[SPLIT * NN * D];
__device__ float g_m[SPLIT * NN];
__device__ float g_l[SPLIT * NN];

// ---------------- warp-MMA / async-copy helpers (portable PTX) ----------------
__device__ __forceinline__ uint32_t smem_u32(const void* p) {
    uint32_t a;
    asm("{ .reg .u64 t; cvta.to.shared.u64 t, %1; cvt.u32.u64 %0, t; }" : "=r"(a) : "l"(p));
    return a;
}
__device__ __forceinline__ void ldsm4(uint32_t r[4], uint32_t addr) {
    asm volatile("ldmatrix.sync.aligned.m8n8.x4.shared.b16 {%0,%1,%2,%3}, [%4];"
                 : "=r"(r[0]), "=r"(r[1]), "=r"(r[2]), "=r"(r[3]) : "r"(addr));
}
__device__ __forceinline__ void mma16816(float d[4], const uint32_t a[4],
                                         uint32_t b0, uint32_t b1) {
    asm volatile("mma.sync.aligned.m16n8k16.row.col.f32.bf16.bf16.f32 "
                 "{%0,%1,%2,%3}, {%4,%5,%6,%7}, {%8,%9}, {%0,%1,%2,%3};"
                 : "+f"(d[0]), "+f"(d[1]), "+f"(d[2]), "+f"(d[3])
                 : "r"(a[0]), "r"(a[1]), "r"(a[2]), "r"(a[3]), "r"(b0), "r"(b1));
}
__device__ __forceinline__ uint32_t pack_bf16x2(float lo, float hi) {
    uint32_t r;
    asm("cvt.rn.bf16x2.f32 %0, %1, %2;" : "=r"(r) : "f"(hi), "f"(lo));
    return r;
}
__device__ __forceinline__ void cp16(uint32_t dst, const void* src) {
    asm volatile("cp.async.cg.shared.global [%0], [%1], 16;" :: "r"(dst), "l"(src) : "memory");
}
#define CP_COMMIT()  asm volatile("cp.async.commit_group;" ::: "memory")
#define CP_WAIT0()   asm volatile("cp.async.wait_group 0;" ::: "memory")

// SMEM layout (dynamic, 131072 B):
//   Q: 32 KB (persistent). Two 48 KB buffers, each K(16K) + VH(16K) + VL(16K).
#define SM_Q       0
#define SM_BUF     32768
#define BUF_STRIDE 49152
#define BUF_K      0
#define BUF_VH     16384
#define BUF_VL     32768
#define SM_TOTAL   131072

// ---------------------------------------------------------------------------
// Kernel 1: Wh = h @ W (fp32), also emits bf16 copy for Q/K
// ---------------------------------------------------------------------------
__global__ __launch_bounds__(128) void wh_kernel(const float* __restrict__ h,
                                                 const float* __restrict__ W) {
    __shared__ float hs[8][DIN];
    const int r0 = blockIdx.x * 8;
    const int tid = threadIdx.x;
    for (int i = tid; i < 8 * DIN; i += 128) hs[i >> 8][i & 255] = h[r0 * DIN + i];
    __syncthreads();
    float acc[8];
#pragma unroll
    for (int r = 0; r < 8; r++) acc[r] = 0.f;
    for (int k = 0; k < DIN; k++) {
        float w = W[k * D + tid];
#pragma unroll
        for (int r = 0; r < 8; r++) acc[r] = fmaf(hs[r][k], w, acc[r]);
    }
#pragma unroll
    for (int r = 0; r < 8; r++) {
        g_Wh[(r0 + r) * D + tid] = acc[r];
        g_Kbf[(r0 + r) * D + tid] = __float2bfloat16(acc[r]);
    }
}

// ---------------------------------------------------------------------------
// Kernel 2: transpose Wh -> VhiT/VloT (bf16 hi/lo split, dim-major)
// ---------------------------------------------------------------------------
__global__ __launch_bounds__(256) void conv_kernel() {
    __shared__ float ts[32][33];
    const int n0 = blockIdx.x * 32, d0 = blockIdx.y * 32;
    const int tx = threadIdx.x, ty = threadIdx.y;   // 32 x 8
    for (int r = ty; r < 32; r += 8) ts[r][tx] = g_Wh[(n0 + r) * D + d0 + tx];
    __syncthreads();
    for (int dd = ty; dd < 32; dd += 8) {
        float v = ts[tx][dd];
        __nv_bfloat16 hi = __float2bfloat16(v);
        __nv_bfloat16 lo = __float2bfloat16(v - __bfloat162float(hi));
        g_VhiT[(size_t)(d0 + dd) * NN + n0 + tx] = hi;
        g_VloT[(size_t)(d0 + dd) * NN + n0 + tx] = lo;
    }
}

// ---------------------------------------------------------------------------
// Async prefetch of one K/VH/VL tile set into buffer `buf` (swizzled layout).
// ---------------------------------------------------------------------------
__device__ __forceinline__ void prefetch_tile(uint32_t sbase, int buf, int key0, int tid) {
    const uint32_t base = sbase + SM_BUF + buf * BUF_STRIDE;
#pragma unroll
    for (int it = 0; it < 4; it++) {                  // K: 64 rows x 16 chunks
        int i = tid + it * 256;
        int row = i >> 4, ch = i & 15;
        cp16(base + BUF_K + row * 256 + ((ch ^ (row & 7)) << 4),
             g_Kbf + (size_t)(key0 + row) * D + ch * 8);
    }
#pragma unroll
    for (int it = 0; it < 4; it++) {                  // VhiT/VloT: 128 rows x 8 chunks
        int i = tid + it * 256;
        int row = i >> 3, ch = i & 7;
        uint32_t soff = (uint32_t)(row * 128 + ((ch ^ (row & 7)) << 4));
        size_t goff = (size_t)row * NN + key0 + ch * 8;
        cp16(base + BUF_VH + soff, g_VhiT + goff);
        cp16(base + BUF_VL + soff, g_VloT + goff);
    }
    CP_COMMIT();
}

// ---------------------------------------------------------------------------
// Kernel 3: flash attention, warp HMMA + cp.async double buffering.
// grid (64, SPLIT), 256 threads. Warp w owns query rows q0+16w..+15.
// Fragment layouts (mma.m16n8k16): per thread,
//   A: a0=(r,k2) a1=(r+8,k2) a2=(r,k2+8) a3=(r+8,k2+8), r=lane>>2, k2=2*(lane&3)
//   B: b0=(k2,n) b1=(k2+8,n), n=lane>>2
//   C: c0,c1=(r, 2n..+1)  c2,c3=(r+8, 2n..+1)
// ---------------------------------------------------------------------------
__global__ __launch_bounds__(256, 1) void attn_kernel() {
    extern __shared__ char smem[];
    const uint32_t sbase = smem_u32(smem);
    const int tid = threadIdx.x;
    const int wid = tid >> 5;
    const int lane = tid & 31;
    const int q0 = blockIdx.x * BM;
    const int split = blockIdx.y;
    const int key_base = split * (NN / SPLIT);

    // ---- kick off prefetch of tile 0 immediately ----
    prefetch_tile(sbase, 0, key_base, tid);

    // ---- load Q tile into smem (swizzled), regular stores ----
    for (int i = tid; i < 2048; i += 256) {           // 128 rows x 16 chunks
        int row = i >> 4, ch = i & 15;
        const uint4 v = *(const uint4*)(g_Kbf + (size_t)(q0 + row) * D + ch * 8);
        *(uint4*)(smem + SM_Q + row * 256 + ((ch ^ (row & 7)) << 4)) = v;
    }
    __syncthreads();

    // ---- Q fragments into registers (held for whole kernel) ----
    uint32_t qf[8][4];
    {
        int arow = 16 * wid + (lane & 15);
        int achb = lane >> 4;
#pragma unroll
        for (int k = 0; k < 8; k++) {
            int ch = 2 * k + achb;
            uint32_t addr = sbase + SM_Q + arow * 256 + ((ch ^ (arow & 7)) << 4);
            ldsm4(qf[k], addr);
        }
    }

    // B-fragment ldmatrix lane addressing:
    // lane l -> row = n0 + ((l>>4)<<3) + (l&7), chunk = 2k + ((l>>3)&1)
    const int brow_off = ((lane >> 4) << 3) + (lane & 7);
    const int bch_off = (lane >> 3) & 1;

    float o[16][4];
#pragma unroll
    for (int n = 0; n < 16; n++)
#pragma unroll
        for (int j = 0; j < 4; j++) o[n][j] = 0.f;
    float m0r = -1e30f, m1r = -1e30f, l0r = 0.f, l1r = 0.f;

    for (int kt = 0; kt < KT_PER; kt++) {
        // tile kt data ready + all warps done reading the other buffer
        CP_WAIT0();
        __syncthreads();

        // prefetch next tile into the other buffer (overlaps this compute)
        if (kt + 1 < KT_PER)
            prefetch_tile(sbase, (kt + 1) & 1, key_base + (kt + 1) * BN, tid);

        const uint32_t bufb = sbase + SM_BUF + (kt & 1) * BUF_STRIDE;

        // ---- S = Q @ K^T : 8 ntiles (n8) x 8 ktiles (k16) ----
        float s[8][4];
#pragma unroll
        for (int n = 0; n < 8; n++)
#pragma unroll
            for (int j = 0; j < 4; j++) s[n][j] = 0.f;
#pragma unroll
        for (int np = 0; np < 4; np++) {              // pair of n8 tiles
            int brow = 16 * np + brow_off;
            uint32_t rbase = bufb + BUF_K + brow * 256;
            int bsw = brow & 7;
#pragma unroll
            for (int k = 0; k < 8; k++) {
                int ch = 2 * k + bch_off;
                uint32_t b[4];
                ldsm4(b, rbase + ((ch ^ bsw) << 4));
                mma16816(s[2 * np], qf[k], b[0], b[1]);
                mma16816(s[2 * np + 1], qf[k], b[2], b[3]);
            }
        }

        // ---- leaky_relu + online softmax (rows r=lane>>2 and r+8) ----
#pragma unroll
        for (int n = 0; n < 8; n++)
#pragma unroll
            for (int j = 0; j < 4; j++)
                s[n][j] = fmaxf(s[n][j], NEG_SLOPE * s[n][j]);

        float mx0 = -1e30f, mx1 = -1e30f;
#pragma unroll
        for (int n = 0; n < 8; n++) {
            mx0 = fmaxf(mx0, fmaxf(s[n][0], s[n][1]));
            mx1 = fmaxf(mx1, fmaxf(s[n][2], s[n][3]));
        }
        mx0 = fmaxf(mx0, __shfl_xor_sync(0xffffffffu, mx0, 1));
        mx0 = fmaxf(mx0, __shfl_xor_sync(0xffffffffu, mx0, 2));
        mx1 = fmaxf(mx1, __shfl_xor_sync(0xffffffffu, mx1, 1));
        mx1 = fmaxf(mx1, __shfl_xor_sync(0xffffffffu, mx1, 2));

        float mn0 = fmaxf(m0r, mx0), mn1 = fmaxf(m1r, mx1);
        float a0 = __expf(m0r - mn0), a1 = __expf(m1r - mn1);
        m0r = mn0; m1r = mn1;

        // lazy rescale of O (running max rarely grows for peaked softmax)
        if (kt > 0) {
            unsigned need = __ballot_sync(0xffffffffu, (a0 != 1.f) || (a1 != 1.f));
            if (need) {
#pragma unroll
                for (int n = 0; n < 16; n++) {
                    o[n][0] *= a0; o[n][1] *= a0;
                    o[n][2] *= a1; o[n][3] *= a1;
                }
            }
        }

        float ps0 = 0.f, ps1 = 0.f;
#pragma unroll
        for (int n = 0; n < 8; n++) {
            s[n][0] = __expf(s[n][0] - mn0);
            s[n][1] = __expf(s[n][1] - mn0);
            s[n][2] = __expf(s[n][2] - mn1);
            s[n][3] = __expf(s[n][3] - mn1);
            ps0 += s[n][0] + s[n][1];
            ps1 += s[n][2] + s[n][3];
        }
        ps0 += __shfl_xor_sync(0xffffffffu, ps0, 1);
        ps0 += __shfl_xor_sync(0xffffffffu, ps0, 2);
        ps1 += __shfl_xor_sync(0xffffffffu, ps1, 1);
        ps1 += __shfl_xor_sync(0xffffffffu, ps1, 2);
        l0r = l0r * a0 + ps0;
        l1r = l1r * a1 + ps1;

        // ---- P fragments: S accum frag -> A operand frag (bf16) ----
        uint32_t pA[4][4];    // 4 k16-tiles over seq(=BN), A layout
#pragma unroll
        for (int j = 0; j < 4; j++) {
            pA[j][0] = pack_bf16x2(s[2 * j][0], s[2 * j][1]);
            pA[j][1] = pack_bf16x2(s[2 * j][2], s[2 * j][3]);
            pA[j][2] = pack_bf16x2(s[2 * j + 1][0], s[2 * j + 1][1]);
            pA[j][3] = pack_bf16x2(s[2 * j + 1][2], s[2 * j + 1][3]);
        }

        // ---- O += P @ Vhi^T, P @ Vlo^T : 8 npairs (d) x 4 ktiles (seq) ----
#pragma unroll
        for (int np = 0; np < 8; np++) {
            int brow = 16 * np + brow_off;
            int bsw = brow & 7;
            uint32_t rh = bufb + BUF_VH + brow * 128;
            uint32_t rl = bufb + BUF_VL + brow * 128;
#pragma unroll
            for (int j = 0; j < 4; j++) {
                int ch = 2 * j + bch_off;
                uint32_t sw = (uint32_t)((ch ^ bsw) << 4);
                uint32_t b[4];
                ldsm4(b, rh + sw);
                mma16816(o[2 * np], pA[j], b[0], b[1]);
                mma16816(o[2 * np + 1], pA[j], b[2], b[3]);
                ldsm4(b, rl + sw);
                mma16816(o[2 * np], pA[j], b[0], b[1]);
                mma16816(o[2 * np + 1], pA[j], b[2], b[3]);
            }
        }
        __syncthreads();   // all warps done with this buffer before next overwrite
    }

    // ---- epilogue: dump unnormalized O + (m, l) partials ----
    const int r0 = q0 + 16 * wid + (lane >> 2);
    const int cb = 2 * (lane & 3);
    float* ob = &g_Opart[((size_t)split * NN + r0) * D];
#pragma unroll
    for (int n = 0; n < 16; n++) {
        *(float2*)&ob[8 * n + cb] = make_float2(o[n][0], o[n][1]);
        *(float2*)&ob[8 * D + 8 * n + cb] = make_float2(o[n][2], o[n][3]);  // row r0+8
    }
    if ((lane & 3) == 0) {
        g_m[split * NN + r0] = m0r;
        g_l[split * NN + r0] = l0r;
        g_m[split * NN + r0 + 8] = m1r;
        g_l[split * NN + r0 + 8] = l1r;
    }
}

// ---------------------------------------------------------------------------
// Kernel 4: combine the SPLIT partials
// ---------------------------------------------------------------------------
__global__ __launch_bounds__(128) void combine_kernel(float* __restrict__ out) {
    const int r = blockIdx.x, c = threadIdx.x;
    float m0 = g_m[r], m1 = g_m[NN + r];
    float m = fmaxf(m0, m1);
    float w0 = __expf(m0 - m), w1 = __expf(m1 - m);
    float l = g_l[r] * w0 + g_l[NN + r] * w1;
    float o = g_Opart[(size_t)r * D + c] * w0 + g_Opart[(size_t)(NN + r) * D + c] * w1;
    out[(size_t)r * D + c] = o / l;
}

// ---------------------------------------------------------------------------
extern "C" void kernel_launch(void* const* d_in, const int* in_sizes, int n_in,
                              void* d_out, int out_size) {
    const float* h = (const float*)d_in[0];
    // d_in[1] = adj: unused by the math, never touched
    const float* W = (const float*)d_in[2];
    float* out = (float*)d_out;

    cudaFuncSetAttribute(attn_kernel, cudaFuncAttributeMaxDynamicSharedMemorySize, SM_TOTAL);

    wh_kernel<<<NN / 8, 128>>>(h, W);
    conv_kernel<<<dim3(NN / 32, D / 32), dim3(32, 8)>>>();
    attn_kernel<<<dim3(NN / BM, SPLIT), 256, SM_TOTAL>>>();
    combine_kernel<<<NN, 128>>>(out);
}

// round 10
// speedup vs baseline: 10.1881x; 1.3017x over previous
#include <cuda_runtime.h>
#include <cuda_bf16.h>
#include <cuda_fp16.h>
#include <cstdint>

// GraphAttentionLayer: out = softmax(leaky_relu(Wh @ Wh^T)) @ Wh, Wh = h @ W
// N=8192, DIN=256, D=128. Flash attention on warp-level HMMA with cp.async
// double-buffered tiles. QK^T in bf16 (safe: softmax gap >> score error),
// PV in fp16 (V quantization ~1.2e-4 rel, the dominant output error, 8x under
// the 1e-3 threshold). fp32 softmax. Split-K=2 over keys + combine.

#define NN 8192
#define DIN 256
#define D 128
#define BM 128          // query rows per CTA (16 per warp, 8 warps)
#define BN 64           // key rows per tile
#define SPLIT 2
#define KT_PER (NN / BN / SPLIT)   // 64 key tiles per CTA
#define NEG_SLOPE 0.2f

// ---------------- device scratch (no allocations allowed) ----------------
__device__ __align__(16) float          g_Wh[NN * D];       // fp32 Wh
__device__ __align__(16) __nv_bfloat16  g_Kbf[NN * D];      // bf16 Wh (Q and K)
__device__ __align__(16) __half         g_VT[D * NN];       // V^T fp16 (dim-major)
__device__ __align__(16) float          g_Opart[SPLIT * NN * D];
__device__ float g_m[SPLIT * NN];
__device__ float g_l[SPLIT * NN];

// ---------------- warp-MMA / async-copy helpers (portable PTX) ----------------
__device__ __forceinline__ uint32_t smem_u32(const void* p) {
    uint32_t a;
    asm("{ .reg .u64 t; cvta.to.shared.u64 t, %1; cvt.u32.u64 %0, t; }" : "=r"(a) : "l"(p));
    return a;
}
__device__ __forceinline__ void ldsm4(uint32_t r[4], uint32_t addr) {
    asm volatile("ldmatrix.sync.aligned.m8n8.x4.shared.b16 {%0,%1,%2,%3}, [%4];"
                 : "=r"(r[0]), "=r"(r[1]), "=r"(r[2]), "=r"(r[3]) : "r"(addr));
}
__device__ __forceinline__ void mma_bf16(float d[4], const uint32_t a[4],
                                         uint32_t b0, uint32_t b1) {
    asm volatile("mma.sync.aligned.m16n8k16.row.col.f32.bf16.bf16.f32 "
                 "{%0,%1,%2,%3}, {%4,%5,%6,%7}, {%8,%9}, {%0,%1,%2,%3};"
                 : "+f"(d[0]), "+f"(d[1]), "+f"(d[2]), "+f"(d[3])
                 : "r"(a[0]), "r"(a[1]), "r"(a[2]), "r"(a[3]), "r"(b0), "r"(b1));
}
__device__ __forceinline__ void mma_f16(float d[4], const uint32_t a[4],
                                        uint32_t b0, uint32_t b1) {
    asm volatile("mma.sync.aligned.m16n8k16.row.col.f32.f16.f16.f32 "
                 "{%0,%1,%2,%3}, {%4,%5,%6,%7}, {%8,%9}, {%0,%1,%2,%3};"
                 : "+f"(d[0]), "+f"(d[1]), "+f"(d[2]), "+f"(d[3])
                 : "r"(a[0]), "r"(a[1]), "r"(a[2]), "r"(a[3]), "r"(b0), "r"(b1));
}
__device__ __forceinline__ uint32_t pack_f16x2(float lo, float hi) {
    uint32_t r;
    asm("cvt.rn.f16x2.f32 %0, %1, %2;" : "=r"(r) : "f"(hi), "f"(lo));
    return r;
}
__device__ __forceinline__ void cp16(uint32_t dst, const void* src) {
    asm volatile("cp.async.cg.shared.global [%0], [%1], 16;" :: "r"(dst), "l"(src) : "memory");
}
#define CP_COMMIT()  asm volatile("cp.async.commit_group;" ::: "memory")
#define CP_WAIT0()   asm volatile("cp.async.wait_group 0;" ::: "memory")

// SMEM layout (dynamic, 98304 B):
//   Q: 32 KB (persistent). Two 32 KB buffers, each K(16K) + VT(16K).
#define SM_Q       0
#define SM_BUF     32768
#define BUF_STRIDE 32768
#define BUF_K      0
#define BUF_VT     16384
#define SM_TOTAL   98304

// ---------------------------------------------------------------------------
// Kernel 1: Wh = h @ W (fp32), also emits bf16 copy for Q/K
// ---------------------------------------------------------------------------
__global__ __launch_bounds__(128) void wh_kernel(const float* __restrict__ h,
                                                 const float* __restrict__ W) {
    __shared__ float hs[8][DIN];
    const int r0 = blockIdx.x * 8;
    const int tid = threadIdx.x;
    for (int i = tid; i < 8 * DIN; i += 128) hs[i >> 8][i & 255] = h[r0 * DIN + i];
    __syncthreads();
    float acc[8];
#pragma unroll
    for (int r = 0; r < 8; r++) acc[r] = 0.f;
    for (int k = 0; k < DIN; k++) {
        float w = W[k * D + tid];
#pragma unroll
        for (int r = 0; r < 8; r++) acc[r] = fmaf(hs[r][k], w, acc[r]);
    }
#pragma unroll
    for (int r = 0; r < 8; r++) {
        g_Wh[(r0 + r) * D + tid] = acc[r];
        g_Kbf[(r0 + r) * D + tid] = __float2bfloat16(acc[r]);
    }
}

// ---------------------------------------------------------------------------
// Kernel 2: transpose Wh -> VT (fp16, dim-major)
// ---------------------------------------------------------------------------
__global__ __launch_bounds__(256) void conv_kernel() {
    __shared__ float ts[32][33];
    const int n0 = blockIdx.x * 32, d0 = blockIdx.y * 32;
    const int tx = threadIdx.x, ty = threadIdx.y;   // 32 x 8
    for (int r = ty; r < 32; r += 8) ts[r][tx] = g_Wh[(n0 + r) * D + d0 + tx];
    __syncthreads();
    for (int dd = ty; dd < 32; dd += 8)
        g_VT[(size_t)(d0 + dd) * NN + n0 + tx] = __float2half(ts[tx][dd]);
}

// ---------------------------------------------------------------------------
// Async prefetch of one K/VT tile set into buffer `buf` (swizzled layout).
// ---------------------------------------------------------------------------
__device__ __forceinline__ void prefetch_tile(uint32_t sbase, int buf, int key0, int tid) {
    const uint32_t base = sbase + SM_BUF + buf * BUF_STRIDE;
#pragma unroll
    for (int it = 0; it < 4; it++) {                  // K: 64 rows x 16 chunks
        int i = tid + it * 256;
        int row = i >> 4, ch = i & 15;
        cp16(base + BUF_K + row * 256 + ((ch ^ (row & 7)) << 4),
             g_Kbf + (size_t)(key0 + row) * D + ch * 8);
    }
#pragma unroll
    for (int it = 0; it < 4; it++) {                  // VT: 128 rows x 8 chunks
        int i = tid + it * 256;
        int row = i >> 3, ch = i & 7;
        cp16(base + BUF_VT + (uint32_t)(row * 128 + ((ch ^ (row & 7)) << 4)),
             g_VT + (size_t)row * NN + key0 + ch * 8);
    }
    CP_COMMIT();
}

// ---------------------------------------------------------------------------
// Kernel 3: flash attention, warp HMMA + cp.async double buffering.
// grid (64, SPLIT), 256 threads. Warp w owns query rows q0+16w..+15.
// Fragment layouts (mma.m16n8k16): per thread,
//   A: a0=(r,k2) a1=(r+8,k2) a2=(r,k2+8) a3=(r+8,k2+8), r=lane>>2, k2=2*(lane&3)
//   B: b0=(k2,n) b1=(k2+8,n), n=lane>>2
//   C: c0,c1=(r, 2n..+1)  c2,c3=(r+8, 2n..+1)
// ---------------------------------------------------------------------------
__global__ __launch_bounds__(256, 1) void attn_kernel() {
    extern __shared__ char smem[];
    const uint32_t sbase = smem_u32(smem);
    const int tid = threadIdx.x;
    const int wid = tid >> 5;
    const int lane = tid & 31;
    const int q0 = blockIdx.x * BM;
    const int split = blockIdx.y;
    const int key_base = split * (NN / SPLIT);

    // ---- kick off prefetch of tile 0 immediately ----
    prefetch_tile(sbase, 0, key_base, tid);

    // ---- load Q tile into smem (swizzled), regular stores ----
    for (int i = tid; i < 2048; i += 256) {           // 128 rows x 16 chunks
        int row = i >> 4, ch = i & 15;
        const uint4 v = *(const uint4*)(g_Kbf + (size_t)(q0 + row) * D + ch * 8);
        *(uint4*)(smem + SM_Q + row * 256 + ((ch ^ (row & 7)) << 4)) = v;
    }
    __syncthreads();

    // ---- Q fragments into registers (held for whole kernel) ----
    uint32_t qf[8][4];
    {
        int arow = 16 * wid + (lane & 15);
        int achb = lane >> 4;
#pragma unroll
        for (int k = 0; k < 8; k++) {
            int ch = 2 * k + achb;
            uint32_t addr = sbase + SM_Q + arow * 256 + ((ch ^ (arow & 7)) << 4);
            ldsm4(qf[k], addr);
        }
    }

    // B-fragment ldmatrix lane addressing:
    // lane l -> row = n0 + ((l>>4)<<3) + (l&7), chunk = 2k + ((l>>3)&1)
    const int brow_off = ((lane >> 4) << 3) + (lane & 7);
    const int bch_off = (lane >> 3) & 1;

    float o[16][4];
#pragma unroll
    for (int n = 0; n < 16; n++)
#pragma unroll
        for (int j = 0; j < 4; j++) o[n][j] = 0.f;
    float m0r = -1e30f, m1r = -1e30f, l0r = 0.f, l1r = 0.f;

    for (int kt = 0; kt < KT_PER; kt++) {
        // tile kt data ready; all warps past their reads of the other buffer
        CP_WAIT0();
        __syncthreads();

        const uint32_t bufb = sbase + SM_BUF + (kt & 1) * BUF_STRIDE;

        // ---- S = Q @ K^T : 8 ntiles (n8) x 8 ktiles (k16) ----
        float s[8][4];
#pragma unroll
        for (int n = 0; n < 8; n++)
#pragma unroll
            for (int j = 0; j < 4; j++) s[n][j] = 0.f;
#pragma unroll
        for (int np = 0; np < 4; np++) {              // pair of n8 tiles
            int brow = 16 * np + brow_off;
            uint32_t rbase = bufb + BUF_K + brow * 256;
            int bsw = brow & 7;
#pragma unroll
            for (int k = 0; k < 8; k++) {
                int ch = 2 * k + bch_off;
                uint32_t b[4];
                ldsm4(b, rbase + ((ch ^ bsw) << 4));
                mma_bf16(s[2 * np], qf[k], b[0], b[1]);
                mma_bf16(s[2 * np + 1], qf[k], b[2], b[3]);
            }
        }

        // prefetch next tile (issued after MMAs so it doesn't delay them;
        // latency hidden by softmax + PV below)
        if (kt + 1 < KT_PER)
            prefetch_tile(sbase, (kt + 1) & 1, key_base + (kt + 1) * BN, tid);

        // ---- leaky_relu + online softmax (rows r=lane>>2 and r+8) ----
#pragma unroll
        for (int n = 0; n < 8; n++)
#pragma unroll
            for (int j = 0; j < 4; j++)
                s[n][j] = fmaxf(s[n][j], NEG_SLOPE * s[n][j]);

        float mx0 = -1e30f, mx1 = -1e30f;
#pragma unroll
        for (int n = 0; n < 8; n++) {
            mx0 = fmaxf(mx0, fmaxf(s[n][0], s[n][1]));
            mx1 = fmaxf(mx1, fmaxf(s[n][2], s[n][3]));
        }
        mx0 = fmaxf(mx0, __shfl_xor_sync(0xffffffffu, mx0, 1));
        mx0 = fmaxf(mx0, __shfl_xor_sync(0xffffffffu, mx0, 2));
        mx1 = fmaxf(mx1, __shfl_xor_sync(0xffffffffu, mx1, 1));
        mx1 = fmaxf(mx1, __shfl_xor_sync(0xffffffffu, mx1, 2));

        float mn0 = fmaxf(m0r, mx0), mn1 = fmaxf(m1r, mx1);
        float a0 = __expf(m0r - mn0), a1 = __expf(m1r - mn1);
        m0r = mn0; m1r = mn1;

        // lazy rescale of O (running max rarely grows for peaked softmax)
        if (kt > 0) {
            unsigned need = __ballot_sync(0xffffffffu, (a0 != 1.f) || (a1 != 1.f));
            if (need) {
#pragma unroll
                for (int n = 0; n < 16; n++) {
                    o[n][0] *= a0; o[n][1] *= a0;
                    o[n][2] *= a1; o[n][3] *= a1;
                }
            }
        }

        float ps0 = 0.f, ps1 = 0.f;
#pragma unroll
        for (int n = 0; n < 8; n++) {
            s[n][0] = __expf(s[n][0] - mn0);
            s[n][1] = __expf(s[n][1] - mn0);
            s[n][2] = __expf(s[n][2] - mn1);
            s[n][3] = __expf(s[n][3] - mn1);
            ps0 += s[n][0] + s[n][1];
            ps1 += s[n][2] + s[n][3];
        }
        ps0 += __shfl_xor_sync(0xffffffffu, ps0, 1);
        ps0 += __shfl_xor_sync(0xffffffffu, ps0, 2);
        ps1 += __shfl_xor_sync(0xffffffffu, ps1, 1);
        ps1 += __shfl_xor_sync(0xffffffffu, ps1, 2);
        l0r = l0r * a0 + ps0;
        l1r = l1r * a1 + ps1;

        // ---- P fragments: S accum frag -> A operand frag (fp16) ----
        uint32_t pA[4][4];    // 4 k16-tiles over seq(=BN), A layout
#pragma unroll
        for (int j = 0; j < 4; j++) {
            pA[j][0] = pack_f16x2(s[2 * j][0], s[2 * j][1]);
            pA[j][1] = pack_f16x2(s[2 * j][2], s[2 * j][3]);
            pA[j][2] = pack_f16x2(s[2 * j + 1][0], s[2 * j + 1][1]);
            pA[j][3] = pack_f16x2(s[2 * j + 1][2], s[2 * j + 1][3]);
        }

        // ---- O += P @ V^T : 8 npairs (d) x 4 ktiles (seq) ----
#pragma unroll
        for (int np = 0; np < 8; np++) {
            int brow = 16 * np + brow_off;
            int bsw = brow & 7;
            uint32_t rv = bufb + BUF_VT + brow * 128;
#pragma unroll
            for (int j = 0; j < 4; j++) {
                int ch = 2 * j + bch_off;
                uint32_t b[4];
                ldsm4(b, rv + (uint32_t)((ch ^ bsw) << 4));
                mma_f16(o[2 * np], pA[j], b[0], b[1]);
                mma_f16(o[2 * np + 1], pA[j], b[2], b[3]);
            }
        }
        // (no end-of-loop barrier: the top-of-loop barrier in iteration kt+1
        //  orders all warps' reads of this buffer before kt+2's prefetch hits it)
    }

    // ---- epilogue: dump unnormalized O + (m, l) partials ----
    const int r0 = q0 + 16 * wid + (lane >> 2);
    const int cb = 2 * (lane & 3);
    float* ob = &g_Opart[((size_t)split * NN + r0) * D];
#pragma unroll
    for (int n = 0; n < 16; n++) {
        *(float2*)&ob[8 * n + cb] = make_float2(o[n][0], o[n][1]);
        *(float2*)&ob[8 * D + 8 * n + cb] = make_float2(o[n][2], o[n][3]);  // row r0+8
    }
    if ((lane & 3) == 0) {
        g_m[split * NN + r0] = m0r;
        g_l[split * NN + r0] = l0r;
        g_m[split * NN + r0 + 8] = m1r;
        g_l[split * NN + r0 + 8] = l1r;
    }
}

// ---------------------------------------------------------------------------
// Kernel 4: combine the SPLIT partials
// ---------------------------------------------------------------------------
__global__ __launch_bounds__(128) void combine_kernel(float* __restrict__ out) {
    const int r = blockIdx.x, c = threadIdx.x;
    float m0 = g_m[r], m1 = g_m[NN + r];
    float m = fmaxf(m0, m1);
    float w0 = __expf(m0 - m), w1 = __expf(m1 - m);
    float l = g_l[r] * w0 + g_l[NN + r] * w1;
    float o = g_Opart[(size_t)r * D + c] * w0 + g_Opart[(size_t)(NN + r) * D + c] * w1;
    out[(size_t)r * D + c] = o / l;
}

// ---------------------------------------------------------------------------
extern "C" void kernel_launch(void* const* d_in, const int* in_sizes, int n_in,
                              void* d_out, int out_size) {
    const float* h = (const float*)d_in[0];
    // d_in[1] = adj: unused by the math, never touched
    const float* W = (const float*)d_in[2];
    float* out = (float*)d_out;

    cudaFuncSetAttribute(attn_kernel, cudaFuncAttributeMaxDynamicSharedMemorySize, SM_TOTAL);

    wh_kernel<<<NN / 8, 128>>>(h, W);
    conv_kernel<<<dim3(NN / 32, D / 32), dim3(32, 8)>>>();
    attn_kernel<<<dim3(NN / BM, SPLIT), 256, SM_TOTAL>>>();
    combine_kernel<<<NN, 128>>>(out);
}